// round 3
// baseline (speedup 1.0000x reference)
#include <cuda_runtime.h>
#include <cuda_bf16.h>

#define KMIX 10

// Compute component index k for one pixel, arithmetic byte-identical to the
// JAX reference: fp32 max-subtract softmax, expf, sequential sum, IEEE div,
// sequential cumsum, strict '<', clip.
__device__ __forceinline__ int pick_k(const float l[KMIX], float u)
{
    float m = l[0];
#pragma unroll
    for (int j = 1; j < KMIX; j++) m = fmaxf(m, l[j]);

    float e[KMIX];
    float S = 0.0f;
#pragma unroll
    for (int j = 0; j < KMIX; j++) {
        e[j] = expf(__fadd_rn(l[j], -m));
        S = __fadd_rn(S, e[j]);
    }

    float cdf = 0.0f;
    int k = 0;
#pragma unroll
    for (int j = 0; j < KMIX; j++) {
        float pj = __fdiv_rn(e[j], S);
        cdf = __fadd_rn(cdf, pj);
        k += (cdf < u) ? 1 : 0;
    }
    return (k > KMIX - 1) ? (KMIX - 1) : k;
}

__global__ void __launch_bounds__(256) melnet_gmm_sample_kernel4(
    const float* __restrict__ mu,
    const float* __restrict__ log_std,
    const float* __restrict__ pi_logits,
    const float* __restrict__ u_cat,
    const float* __restrict__ eps,
    float* __restrict__ out,
    int n)   // n = number of PIXEL QUADS
{
    int t = blockIdx.x * blockDim.x + threadIdx.x;
    if (t >= n) return;

    // four adjacent rows = 160 B, 16B-aligned -> ten LDG.128, front-batched
    const float4* pl = reinterpret_cast<const float4*>(pi_logits) + (size_t)t * 10;
    float4 q[10];
#pragma unroll
    for (int i = 0; i < 10; i++) q[i] = __ldg(pl + i);

    float4 u4 = __ldg(reinterpret_cast<const float4*>(u_cat) + t);
    float4 e4 = __ldg(reinterpret_cast<const float4*>(eps) + t);

    // unpack 40 logits into 4 rows of 10
    float lg[40];
#pragma unroll
    for (int i = 0; i < 10; i++) {
        lg[4*i + 0] = q[i].x;
        lg[4*i + 1] = q[i].y;
        lg[4*i + 2] = q[i].z;
        lg[4*i + 3] = q[i].w;
    }

    const float uu[4] = { u4.x, u4.y, u4.z, u4.w };
    const float ee[4] = { e4.x, e4.y, e4.z, e4.w };

    // compute all 4 component indices first
    int kk[4];
#pragma unroll
    for (int px = 0; px < 4; px++) {
        float l[KMIX];
#pragma unroll
        for (int j = 0; j < KMIX; j++) l[j] = lg[px * KMIX + j];
        kk[px] = pick_k(l, uu[px]);
    }

    // issue all 8 independent gathers together (deep DRAM queue, good MLP)
    int base = 4 * t * KMIX;
    float mu_k[4], ls_k[4];
#pragma unroll
    for (int px = 0; px < 4; px++) {
        int idx = base + px * KMIX + kk[px];
        mu_k[px] = __ldg(mu + idx);
        ls_k[px] = __ldg(log_std + idx);
    }

    float4 o;
    o.x = __fadd_rn(mu_k[0], __fmul_rn(expf(ls_k[0]), ee[0]));
    o.y = __fadd_rn(mu_k[1], __fmul_rn(expf(ls_k[1]), ee[1]));
    o.z = __fadd_rn(mu_k[2], __fmul_rn(expf(ls_k[2]), ee[2]));
    o.w = __fadd_rn(mu_k[3], __fmul_rn(expf(ls_k[3]), ee[3]));

    reinterpret_cast<float4*>(out)[t] = o;
}

extern "C" void kernel_launch(void* const* d_in, const int* in_sizes, int n_in,
                              void* d_out, int out_size)
{
    // metadata order: mu, log_std, pi_logits, u_cat, eps
    const float* mu        = (const float*)d_in[0];
    const float* log_std   = (const float*)d_in[1];
    const float* pi_logits = (const float*)d_in[2];
    const float* u_cat     = (const float*)d_in[3];
    const float* eps       = (const float*)d_in[4];
    float* out = (float*)d_out;

    int n = in_sizes[3];       // B*F*T pixels (4,194,304 — divisible by 4)
    int nquads = n / 4;

    int threads = 256;
    int blocks = (nquads + threads - 1) / threads;
    melnet_gmm_sample_kernel4<<<blocks, threads>>>(mu, log_std, pi_logits,
                                                   u_cat, eps, out, nquads);
}

// round 4
// speedup vs baseline: 1.0249x; 1.0249x over previous
#include <cuda_runtime.h>
#include <cuda_bf16.h>

#define KMIX 10

// Component index for one pixel, arithmetic byte-identical to the JAX
// reference: fp32 max-subtract softmax, expf, sequential sum, IEEE div,
// sequential cumsum, strict '<', clip.
__device__ __forceinline__ int pick_k(const float* l, float u)
{
    float m = l[0];
#pragma unroll
    for (int j = 1; j < KMIX; j++) m = fmaxf(m, l[j]);

    float e[KMIX];
    float S = 0.0f;
#pragma unroll
    for (int j = 0; j < KMIX; j++) {
        e[j] = expf(__fadd_rn(l[j], -m));
        S = __fadd_rn(S, e[j]);
    }

    float cdf = 0.0f;
    int k = 0;
#pragma unroll
    for (int j = 0; j < KMIX; j++) {
        float pj = __fdiv_rn(e[j], S);
        cdf = __fadd_rn(cdf, pj);
        k += (cdf < u) ? 1 : 0;
    }
    return (k > KMIX - 1) ? (KMIX - 1) : k;
}

__global__ void __launch_bounds__(256, 6) melnet_gmm_sample_kernel2b(
    const float* __restrict__ mu,
    const float* __restrict__ log_std,
    const float* __restrict__ pi_logits,
    const float* __restrict__ u_cat,
    const float* __restrict__ eps,
    float* __restrict__ out,
    int n)   // n = number of PIXEL PAIRS
{
    int t = blockIdx.x * blockDim.x + threadIdx.x;
    if (t >= n) return;

    // ---- phase 1: front-batch all streaming loads ----
    // two adjacent rows = 80 B, 16B-aligned -> five LDG.128
    const float4* pl = reinterpret_cast<const float4*>(pi_logits) + (size_t)t * 5;
    float4 q0 = __ldg(pl + 0);
    float4 q1 = __ldg(pl + 1);
    float4 q2 = __ldg(pl + 2);
    float4 q3 = __ldg(pl + 3);
    float4 q4 = __ldg(pl + 4);
    float2 u2 = __ldg(reinterpret_cast<const float2*>(u_cat) + t);
    float2 e2 = __ldg(reinterpret_cast<const float2*>(eps) + t);

    float lg[2 * KMIX] = { q0.x, q0.y, q0.z, q0.w,
                           q1.x, q1.y, q1.z, q1.w,
                           q2.x, q2.y,                    // pixel A
                           q2.z, q2.w,
                           q3.x, q3.y, q3.z, q3.w,
                           q4.x, q4.y, q4.z, q4.w };      // pixel B

    // ---- phase 2: compute both component indices ----
    int kA = pick_k(lg,        u2.x);
    int kB = pick_k(lg + KMIX, u2.y);

    // ---- phase 3: all 4 independent gathers issued back-to-back ----
    int base = 2 * t * KMIX;
    int iA = base + kA;
    int iB = base + KMIX + kB;
    float muA = __ldg(mu + iA);
    float muB = __ldg(mu + iB);
    float lsA = __ldg(log_std + iA);
    float lsB = __ldg(log_std + iB);

    // ---- phase 4: epilogue (mul-then-add, no FMA contraction) ----
    float2 o;
    o.x = __fadd_rn(muA, __fmul_rn(expf(lsA), e2.x));
    o.y = __fadd_rn(muB, __fmul_rn(expf(lsB), e2.y));
    reinterpret_cast<float2*>(out)[t] = o;
}

extern "C" void kernel_launch(void* const* d_in, const int* in_sizes, int n_in,
                              void* d_out, int out_size)
{
    // metadata order: mu, log_std, pi_logits, u_cat, eps
    const float* mu        = (const float*)d_in[0];
    const float* log_std   = (const float*)d_in[1];
    const float* pi_logits = (const float*)d_in[2];
    const float* u_cat     = (const float*)d_in[3];
    const float* eps       = (const float*)d_in[4];
    float* out = (float*)d_out;

    int n = in_sizes[3];       // B*F*T pixels (4,194,304 — even)
    int npairs = n / 2;

    int threads = 256;
    int blocks = (npairs + threads - 1) / threads;
    melnet_gmm_sample_kernel2b<<<blocks, threads>>>(mu, log_std, pi_logits,
                                                    u_cat, eps, out, npairs);
}

// round 5
// speedup vs baseline: 1.0511x; 1.0255x over previous
#include <cuda_runtime.h>
#include <cuda_bf16.h>

#define KMIX 10

__global__ void __launch_bounds__(256) melnet_gmm_stream_kernel(
    const float* __restrict__ mu,
    const float* __restrict__ log_std,
    const float* __restrict__ pi_logits,
    const float* __restrict__ u_cat,
    const float* __restrict__ eps,
    float* __restrict__ out,
    int n)
{
    int p = blockIdx.x * blockDim.x + threadIdx.x;
    if (p >= n) return;

    // ---- front-batch ALL loads: 3 full 40B rows + u + eps (17 loads, pure stream) ----
    const float2* pp = reinterpret_cast<const float2*>(pi_logits) + (size_t)p * 5;
    const float2* pm = reinterpret_cast<const float2*>(mu)        + (size_t)p * 5;
    const float2* ps = reinterpret_cast<const float2*>(log_std)   + (size_t)p * 5;

    float2 q[5], r[5], s[5];
#pragma unroll
    for (int i = 0; i < 5; i++) q[i] = __ldg(pp + i);
#pragma unroll
    for (int i = 0; i < 5; i++) r[i] = __ldg(pm + i);
#pragma unroll
    for (int i = 0; i < 5; i++) s[i] = __ldg(ps + i);
    float u  = __ldg(u_cat + p);
    float ep = __ldg(eps + p);

    float l[KMIX]  = { q[0].x, q[0].y, q[1].x, q[1].y, q[2].x,
                       q[2].y, q[3].x, q[3].y, q[4].x, q[4].y };
    float mg[KMIX] = { r[0].x, r[0].y, r[1].x, r[1].y, r[2].x,
                       r[2].y, r[3].x, r[3].y, r[4].x, r[4].y };
    float sg[KMIX] = { s[0].x, s[0].y, s[1].x, s[1].y, s[2].x,
                       s[2].y, s[3].x, s[3].y, s[4].x, s[4].y };

    // ---- softmax + inverse-CDF pick, arithmetic byte-identical to reference ----
    float m = l[0];
#pragma unroll
    for (int j = 1; j < KMIX; j++) m = fmaxf(m, l[j]);

    float e[KMIX];
    float S = 0.0f;
#pragma unroll
    for (int j = 0; j < KMIX; j++) {
        e[j] = expf(__fadd_rn(l[j], -m));
        S = __fadd_rn(S, e[j]);
    }

    float cdf = 0.0f;
    int k = 0;
#pragma unroll
    for (int j = 0; j < KMIX; j++) {
        float pj = __fdiv_rn(e[j], S);     // exact IEEE division, matching reference
        cdf = __fadd_rn(cdf, pj);
        k += (cdf < u) ? 1 : 0;
    }
    if (k > KMIX - 1) k = KMIX - 1;

    // ---- in-register selection (bit-identical to a memory gather of element k) ----
    float mu_k = mg[0];
    float ls_k = sg[0];
#pragma unroll
    for (int j = 1; j < KMIX; j++) {
        bool sel = (j == k);
        mu_k = sel ? mg[j] : mu_k;
        ls_k = sel ? sg[j] : ls_k;
    }

    // out = mu_k + exp(ls_k) * eps  (explicit mul-then-add, no FMA contraction)
    out[p] = __fadd_rn(mu_k, __fmul_rn(expf(ls_k), ep));
}

extern "C" void kernel_launch(void* const* d_in, const int* in_sizes, int n_in,
                              void* d_out, int out_size)
{
    // metadata order: mu, log_std, pi_logits, u_cat, eps
    const float* mu        = (const float*)d_in[0];
    const float* log_std   = (const float*)d_in[1];
    const float* pi_logits = (const float*)d_in[2];
    const float* u_cat     = (const float*)d_in[3];
    const float* eps       = (const float*)d_in[4];
    float* out = (float*)d_out;

    int n = in_sizes[3];   // B*F*T pixels

    int threads = 256;
    int blocks = (n + threads - 1) / threads;
    melnet_gmm_stream_kernel<<<blocks, threads>>>(mu, log_std, pi_logits,
                                                  u_cat, eps, out, n);
}